// round 3
// baseline (speedup 1.0000x reference)
#include <cuda_runtime.h>
#include <cuda_bf16.h>

#define D 64
#define K 1024
#define N_POINTS 65536   // 16 * 64 * 64
#define HW 4096          // 64*64
#define CHUNK 128

__device__ float g_cnorm[K];         // 0.5 * ||e_k||^2
__device__ float g_counts[K];        // per-code hit counts (float, exact < 2^24)
__device__ float g_embupd[D * K];    // segment-sum of z per code

// ---------------------------------------------------------------------------
// Kernel 0: code norms + zero scratch.  <<<4, 256>>>
// ---------------------------------------------------------------------------
__global__ void vq_prep(const float* __restrict__ emb) {
    int k = blockIdx.x * 256 + threadIdx.x;   // 0..1023
    float s = 0.0f;
#pragma unroll
    for (int d = 0; d < D; d++) {
        float e = emb[d * K + k];
        s = fmaf(e, e, s);
    }
    g_cnorm[k] = 0.5f * s;
    g_counts[k] = 0.0f;
#pragma unroll
    for (int d = 0; d < D; d++) g_embupd[d * K + k] = 0.0f;
}

// ---------------------------------------------------------------------------
// Kernel 1: nearest code per point + scatter + z_q + idx.  <<<256, 256>>>
// ---------------------------------------------------------------------------
__global__ void __launch_bounds__(256)
vq_assign(const float* __restrict__ z_e, const float* __restrict__ emb,
          float* __restrict__ zq, float* __restrict__ idxf) {
    __shared__ float s_emb[D * CHUNK];
    __shared__ float s_cn[CHUNK];

    const int tid = threadIdx.x;
    const int n = blockIdx.x * 256 + tid;
    const int b = n >> 12;          // n / 4096
    const int hw = n & (HW - 1);

    const float* zp = z_e + (size_t)b * D * HW + hw;
    float z[D];
#pragma unroll
    for (int d = 0; d < D; d++) z[d] = zp[d * HW];

    float best = -3.0e38f;
    int bi = 0;

    for (int k0 = 0; k0 < K; k0 += CHUNK) {
        __syncthreads();
        // cooperative load of emb chunk [D][CHUNK] into smem (float4, coalesced)
#pragma unroll
        for (int i = 0; i < (D * CHUNK / 4) / 256; i++) {   // 8 iters
            int v = tid + i * 256;        // float4 index, 0..2047
            int d = v >> 5;               // (4v)/128
            int c = (v & 31) * 4;         // (4v)%128
            *(float4*)(s_emb + d * CHUNK + c) =
                *(const float4*)(emb + d * K + k0 + c);
        }
        if (tid < CHUNK) s_cn[tid] = g_cnorm[k0 + tid];
        __syncthreads();

        for (int c4 = 0; c4 < CHUNK / 4; c4++) {
            float4 acc = make_float4(0.f, 0.f, 0.f, 0.f);
#pragma unroll
            for (int d = 0; d < D; d++) {
                float4 e = *(const float4*)(s_emb + d * CHUNK + c4 * 4);
                acc.x = fmaf(z[d], e.x, acc.x);
                acc.y = fmaf(z[d], e.y, acc.y);
                acc.z = fmaf(z[d], e.z, acc.z);
                acc.w = fmaf(z[d], e.w, acc.w);
            }
            const int cb = k0 + c4 * 4;
            float s0 = acc.x - s_cn[c4 * 4 + 0];
            float s1 = acc.y - s_cn[c4 * 4 + 1];
            float s2 = acc.z - s_cn[c4 * 4 + 2];
            float s3 = acc.w - s_cn[c4 * 4 + 3];
            // strict '>' keeps the FIRST index on ties (matches argmin)
            if (s0 > best) { best = s0; bi = cb + 0; }
            if (s1 > best) { best = s1; bi = cb + 1; }
            if (s2 > best) { best = s2; bi = cb + 2; }
            if (s3 > best) { best = s3; bi = cb + 3; }
        }
    }

    idxf[n] = (float)bi;
    atomicAdd(&g_counts[bi], 1.0f);

    float* zqp = zq + (size_t)b * D * HW + hw;
#pragma unroll
    for (int d = 0; d < D; d++) {
        atomicAdd(&g_embupd[d * K + bi], z[d]);
        zqp[d * HW] = emb[d * K + bi];   // z_q == selected embedding (L2-hit gather)
    }
}

// ---------------------------------------------------------------------------
// Kernel 2: EMA update + renorm.  <<<1, 1024>>>
// ---------------------------------------------------------------------------
__global__ void vq_finalize(const float* __restrict__ emb_ema,
                            const float* __restrict__ counts_ema,
                            float* __restrict__ out_emb_new,
                            float* __restrict__ out_emb_ema_new,
                            float* __restrict__ out_counts_new) {
    const float ALPHA = (float)(1.0 - 0.99);       // 1 - DECAY, double-rounded
    const float EPSF = 1e-5f;
    const float KEPS = (float)(1024.0 * 1e-5);

    __shared__ float red[1024];
    int k = threadIdx.x;

    float cen = counts_ema[k] + ALPHA * (g_counts[k] - counts_ema[k]);
    out_counts_new[k] = cen;

    red[k] = cen;
    __syncthreads();
#pragma unroll
    for (int s = 512; s > 0; s >>= 1) {
        if (k < s) red[k] += red[k + s];
        __syncthreads();
    }
    float nsum = red[0];

    float cn = (cen + EPSF) / (nsum + KEPS) * nsum;
    float inv = 1.0f / cn;

#pragma unroll
    for (int d = 0; d < D; d++) {
        float eu = g_embupd[d * K + k];
        float ee = emb_ema[d * K + k];
        float en = ee + ALPHA * (eu - ee);
        out_emb_ema_new[d * K + k] = en;
        out_emb_new[d * K + k] = en * inv;
    }
}

// ---------------------------------------------------------------------------
extern "C" void kernel_launch(void* const* d_in, const int* in_sizes, int n_in,
                              void* d_out, int out_size) {
    const float* z_e        = (const float*)d_in[0];   // [16,64,64,64]
    const float* emb        = (const float*)d_in[1];   // [64,1024]
    const float* emb_ema    = (const float*)d_in[2];   // [64,1024]
    const float* counts_ema = (const float*)d_in[3];   // [1024]

    float* out = (float*)d_out;
    float* o_zq         = out;                          // 4,194,304
    float* o_idx        = out + 4194304;                // 65,536
    float* o_emb_new    = out + 4194304 + 65536;        // 65,536
    float* o_emb_ema    = out + 4194304 + 2 * 65536;    // 65,536
    float* o_counts     = out + 4194304 + 3 * 65536;    // 1,024

    vq_prep<<<4, 256>>>(emb);
    vq_assign<<<N_POINTS / 256, 256>>>(z_e, emb, o_zq, o_idx);
    vq_finalize<<<1, 1024>>>(emb_ema, counts_ema, o_emb_new, o_emb_ema, o_counts);
}

// round 4
// speedup vs baseline: 1.0062x; 1.0062x over previous
#include <cuda_runtime.h>
#include <cuda_bf16.h>

#define D 64
#define K 1024
#define N_POINTS 65536   // 16 * 64 * 64
#define HW 4096          // 64*64
#define CHUNK 128
#define BT 64            // threads per block (small tiles -> good wave balance)

__device__ float g_cnorm[K];         // 0.5 * ||e_k||^2
__device__ float g_counts[K];        // per-code hit counts
__device__ float g_embupd[D * K];    // segment-sum of z per code

// ---- packed f32x2 helpers (Blackwell sm_103a) ------------------------------
__device__ __forceinline__ unsigned long long pack2(float lo, float hi) {
    unsigned long long r;
    asm("mov.b64 %0, {%1, %2};" : "=l"(r) : "f"(lo), "f"(hi));
    return r;
}
__device__ __forceinline__ void unpack2(unsigned long long v, float& lo, float& hi) {
    asm("mov.b64 {%0, %1}, %2;" : "=f"(lo), "=f"(hi) : "l"(v));
}
__device__ __forceinline__ void fma2(unsigned long long& a,
                                     unsigned long long x, unsigned long long y) {
    asm("fma.rn.f32x2 %0, %1, %2, %0;" : "+l"(a) : "l"(x), "l"(y));
}

// ---------------------------------------------------------------------------
// Kernel 0: code norms + zero scratch.  <<<4, 256>>>
// ---------------------------------------------------------------------------
__global__ void vq_prep(const float* __restrict__ emb) {
    int k = blockIdx.x * 256 + threadIdx.x;   // 0..1023
    float s = 0.0f;
#pragma unroll
    for (int d = 0; d < D; d++) {
        float e = emb[d * K + k];
        s = fmaf(e, e, s);
    }
    g_cnorm[k] = 0.5f * s;
    g_counts[k] = 0.0f;
#pragma unroll
    for (int d = 0; d < D; d++) g_embupd[d * K + k] = 0.0f;
}

// ---------------------------------------------------------------------------
// Kernel 1: nearest code per point + scatter + z_q + idx.  <<<1024, 64>>>
// score(c) = z.e_c - 0.5*||e_c||^2, argmax == argmin of L2 dist.
// Inner loop: 8 codes per d -> 2x LDS.128 + 4x fma.rn.f32x2 (2 FMA/instr).
// ---------------------------------------------------------------------------
__global__ void __launch_bounds__(BT, 4)
vq_assign(const float* __restrict__ z_e, const float* __restrict__ emb,
          float* __restrict__ zq, float* __restrict__ idxf) {
    __shared__ float s_emb[D * CHUNK];                 // 32 KB
    __shared__ unsigned long long s_cnp[CHUNK / 2];    // packed {-cn, -cn}

    const int tid = threadIdx.x;
    const int n = blockIdx.x * BT + tid;
    const int b = n >> 12;          // n / 4096
    const int hw = n & (HW - 1);

    // load z, duplicated into both f32x2 lanes
    const float* zp = z_e + (size_t)b * D * HW + hw;
    unsigned long long zd[D];
#pragma unroll
    for (int d = 0; d < D; d++) {
        float v = zp[d * HW];
        zd[d] = pack2(v, v);
    }

    float best = -3.4e38f;
    int bi = 0;

    for (int k0 = 0; k0 < K; k0 += CHUNK) {
        __syncthreads();
        // cooperative load of emb chunk [D][CHUNK] into smem (float4, coalesced)
#pragma unroll
        for (int i = 0; i < (D * CHUNK / 4) / BT; i++) {   // 32 iters
            int v = tid + i * BT;         // float4 index, 0..2047
            int d = v >> 5;
            int c = (v & 31) * 4;
            *(float4*)(s_emb + d * CHUNK + c) =
                *(const float4*)(emb + d * K + k0 + c);
        }
        // packed negated half-norms: acc starts at -0.5||e||^2 (no epilogue sub)
        {
            float c0 = g_cnorm[k0 + 2 * tid];
            float c1 = g_cnorm[k0 + 2 * tid + 1];
            s_cnp[tid] = pack2(-c0, -c1);
        }
        __syncthreads();

        for (int c8 = 0; c8 < CHUNK / 8; c8++) {
            unsigned long long a0 = s_cnp[c8 * 4 + 0];
            unsigned long long a1 = s_cnp[c8 * 4 + 1];
            unsigned long long a2 = s_cnp[c8 * 4 + 2];
            unsigned long long a3 = s_cnp[c8 * 4 + 3];
            const float* ebase = s_emb + c8 * 8;
#pragma unroll
            for (int d = 0; d < D; d++) {
                ulonglong2 qa = *(const ulonglong2*)(ebase + d * CHUNK);
                ulonglong2 qb = *(const ulonglong2*)(ebase + d * CHUNK + 4);
                fma2(a0, zd[d], qa.x);
                fma2(a1, zd[d], qa.y);
                fma2(a2, zd[d], qb.x);
                fma2(a3, zd[d], qb.y);
            }
            const int cb = k0 + c8 * 8;
            float f0, f1;
            unpack2(a0, f0, f1);
            if (f0 > best) { best = f0; bi = cb + 0; }
            if (f1 > best) { best = f1; bi = cb + 1; }
            unpack2(a1, f0, f1);
            if (f0 > best) { best = f0; bi = cb + 2; }
            if (f1 > best) { best = f1; bi = cb + 3; }
            unpack2(a2, f0, f1);
            if (f0 > best) { best = f0; bi = cb + 4; }
            if (f1 > best) { best = f1; bi = cb + 5; }
            unpack2(a3, f0, f1);
            if (f0 > best) { best = f0; bi = cb + 6; }
            if (f1 > best) { best = f1; bi = cb + 7; }
        }
    }

    idxf[n] = (float)bi;
    atomicAdd(&g_counts[bi], 1.0f);

    float* zqp = zq + (size_t)b * D * HW + hw;
#pragma unroll
    for (int d = 0; d < D; d++) {
        float zv = __uint_as_float((unsigned)(zd[d] & 0xffffffffull));
        atomicAdd(&g_embupd[d * K + bi], zv);
        zqp[d * HW] = emb[d * K + bi];   // z_q == selected embedding (L2 gather)
    }
}

// ---------------------------------------------------------------------------
// Kernel 2: EMA update + renorm.  <<<1, 1024>>>
// ---------------------------------------------------------------------------
__global__ void vq_finalize(const float* __restrict__ emb_ema,
                            const float* __restrict__ counts_ema,
                            float* __restrict__ out_emb_new,
                            float* __restrict__ out_emb_ema_new,
                            float* __restrict__ out_counts_new) {
    const float ALPHA = (float)(1.0 - 0.99);
    const float EPSF = 1e-5f;
    const float KEPS = (float)(1024.0 * 1e-5);

    __shared__ float red[1024];
    int k = threadIdx.x;

    float cen = counts_ema[k] + ALPHA * (g_counts[k] - counts_ema[k]);
    out_counts_new[k] = cen;

    red[k] = cen;
    __syncthreads();
#pragma unroll
    for (int s = 512; s > 0; s >>= 1) {
        if (k < s) red[k] += red[k + s];
        __syncthreads();
    }
    float nsum = red[0];

    float cn = (cen + EPSF) / (nsum + KEPS) * nsum;
    float inv = 1.0f / cn;

#pragma unroll
    for (int d = 0; d < D; d++) {
        float eu = g_embupd[d * K + k];
        float ee = emb_ema[d * K + k];
        float en = ee + ALPHA * (eu - ee);
        out_emb_ema_new[d * K + k] = en;
        out_emb_new[d * K + k] = en * inv;
    }
}

// ---------------------------------------------------------------------------
extern "C" void kernel_launch(void* const* d_in, const int* in_sizes, int n_in,
                              void* d_out, int out_size) {
    const float* z_e        = (const float*)d_in[0];   // [16,64,64,64]
    const float* emb        = (const float*)d_in[1];   // [64,1024]
    const float* emb_ema    = (const float*)d_in[2];   // [64,1024]
    const float* counts_ema = (const float*)d_in[3];   // [1024]

    float* out = (float*)d_out;
    float* o_zq         = out;                          // 4,194,304
    float* o_idx        = out + 4194304;                // 65,536
    float* o_emb_new    = out + 4194304 + 65536;        // 65,536
    float* o_emb_ema    = out + 4194304 + 2 * 65536;    // 65,536
    float* o_counts     = out + 4194304 + 3 * 65536;    // 1,024

    vq_prep<<<4, 256>>>(emb);
    vq_assign<<<N_POINTS / BT, BT>>>(z_e, emb, o_zq, o_idx);
    vq_finalize<<<1, 1024>>>(emb_ema, counts_ema, o_emb_new, o_emb_ema, o_counts);
}

// round 6
// speedup vs baseline: 1.3697x; 1.3612x over previous
#include <cuda_runtime.h>
#include <cuda_bf16.h>

#define D 64
#define K 1024
#define N_POINTS 65536   // 16 * 64 * 64
#define HW 4096          // 64*64
#define CHUNK 128        // codes staged in smem per iteration
#define BTH 128          // threads per block
#define PTS 256          // points per block (P = 2 per thread)
#define CT 16            // code tile per thread

__device__ float g_cnorm[K];         // 0.5 * ||e_k||^2
__device__ float g_counts[K];
__device__ float g_embupd[D * K];

// ---- packed f32x2 helpers (sm_103a) ----------------------------------------
__device__ __forceinline__ unsigned long long pack2(float lo, float hi) {
    unsigned long long r;
    asm("mov.b64 %0, {%1, %2};" : "=l"(r) : "f"(lo), "f"(hi));
    return r;
}
__device__ __forceinline__ void unpack2(unsigned long long v, float& lo, float& hi) {
    asm("mov.b64 {%0, %1}, %2;" : "=f"(lo), "=f"(hi) : "l"(v));
}
__device__ __forceinline__ void fma2(unsigned long long& a,
                                     unsigned long long x, unsigned long long y) {
    asm("fma.rn.f32x2 %0, %1, %2, %0;" : "+l"(a) : "l"(x), "l"(y));
}

// ---------------------------------------------------------------------------
// Kernel 0: code norms + zero scratch.  <<<4, 256>>>
// ---------------------------------------------------------------------------
__global__ void vq_prep(const float* __restrict__ emb) {
    int k = blockIdx.x * 256 + threadIdx.x;
    float s = 0.0f;
#pragma unroll
    for (int d = 0; d < D; d++) {
        float e = emb[d * K + k];
        s = fmaf(e, e, s);
    }
    g_cnorm[k] = 0.5f * s;
    g_counts[k] = 0.0f;
#pragma unroll
    for (int d = 0; d < D; d++) g_embupd[d * K + k] = 0.0f;
}

// ---------------------------------------------------------------------------
// Kernel 1: nearest code per point + scatter + z_q + idx.  <<<256, 128>>>
// Each thread: 2 points x 16-code tiles; per d: 4 LDS.128(e) + 1 LDS.64(z)
// + 16 fma.rn.f32x2.  score = z.e - 0.5||e||^2 (norm folded into acc init).
// ---------------------------------------------------------------------------
__global__ void __launch_bounds__(BTH)
vq_assign(const float* __restrict__ z_e, const float* __restrict__ emb,
          float* __restrict__ zq, float* __restrict__ idxf) {
    __shared__ float s_z[D * PTS];                     // 64 KB  [d][pt]
    __shared__ float s_emb[D * CHUNK];                 // 32 KB  [d][code]
    __shared__ unsigned long long s_cnp[CHUNK / 2];    // packed {-cn,-cn+1}

    const int tid = threadIdx.x;
    const int n0 = blockIdx.x * PTS;       // first point of block
    const int b = n0 >> 12;
    const int hw0 = n0 & (HW - 1);         // multiple of 256
    const float* zbase = z_e + (size_t)b * D * HW + hw0;

    // stage z tile [64 d][256 pts] (coalesced float4)
#pragma unroll
    for (int i = 0; i < (D * PTS / 4) / BTH; i++) {    // 32 iters
        int v = tid + i * BTH;
        int d = v >> 6;                    // PTS/4 = 64 float4 per row
        int c = (v & 63) * 4;
        *(float4*)(s_z + d * PTS + c) = *(const float4*)(zbase + d * HW + c);
    }

    float best0 = -3.4e38f, best1 = -3.4e38f;
    int bi0 = 0, bi1 = 0;

    for (int k0 = 0; k0 < K; k0 += CHUNK) {
        __syncthreads();
#pragma unroll
        for (int i = 0; i < (D * CHUNK / 4) / BTH; i++) {   // 16 iters
            int v = tid + i * BTH;
            int d = v >> 5;
            int c = (v & 31) * 4;
            *(float4*)(s_emb + d * CHUNK + c) =
                *(const float4*)(emb + d * K + k0 + c);
        }
        if (tid < CHUNK / 2) {
            float c0 = g_cnorm[k0 + 2 * tid];
            float c1 = g_cnorm[k0 + 2 * tid + 1];
            s_cnp[tid] = pack2(-c0, -c1);
        }
        __syncthreads();

#pragma unroll
        for (int t = 0; t < CHUNK / CT; t++) {         // 8 code tiles of 16
            unsigned long long a0[CT / 2], a1[CT / 2];
#pragma unroll
            for (int j = 0; j < CT / 2; j++) {
                unsigned long long cn = s_cnp[t * (CT / 2) + j];
                a0[j] = cn;
                a1[j] = cn;
            }
#pragma unroll 8
            for (int d = 0; d < D; d++) {
                // two points' z for this d (consecutive floats)
                unsigned long long zpair =
                    *(const unsigned long long*)(s_z + d * PTS + 2 * tid);
                float z0, z1;
                unpack2(zpair, z0, z1);
                unsigned long long zd0 = pack2(z0, z0);
                unsigned long long zd1 = pack2(z1, z1);

                const ulonglong2* ep =
                    (const ulonglong2*)(s_emb + d * CHUNK + t * CT);
                ulonglong2 ea = ep[0];
                ulonglong2 eb = ep[1];
                ulonglong2 ec = ep[2];
                ulonglong2 ed = ep[3];

                fma2(a0[0], zd0, ea.x); fma2(a1[0], zd1, ea.x);
                fma2(a0[1], zd0, ea.y); fma2(a1[1], zd1, ea.y);
                fma2(a0[2], zd0, eb.x); fma2(a1[2], zd1, eb.x);
                fma2(a0[3], zd0, eb.y); fma2(a1[3], zd1, eb.y);
                fma2(a0[4], zd0, ec.x); fma2(a1[4], zd1, ec.x);
                fma2(a0[5], zd0, ec.y); fma2(a1[5], zd1, ec.y);
                fma2(a0[6], zd0, ed.x); fma2(a1[6], zd1, ed.x);
                fma2(a0[7], zd0, ed.y); fma2(a1[7], zd1, ed.y);
            }
            const int cb = k0 + t * CT;
#pragma unroll
            for (int j = 0; j < CT / 2; j++) {
                float f0, f1;
                unpack2(a0[j], f0, f1);
                if (f0 > best0) { best0 = f0; bi0 = cb + 2 * j; }
                if (f1 > best0) { best0 = f1; bi0 = cb + 2 * j + 1; }
                unpack2(a1[j], f0, f1);
                if (f0 > best1) { best1 = f0; bi1 = cb + 2 * j; }
                if (f1 > best1) { best1 = f1; bi1 = cb + 2 * j + 1; }
            }
        }
    }

    // epilogue: two points per thread
    const int p0 = 2 * tid, p1 = 2 * tid + 1;
    idxf[n0 + p0] = (float)bi0;
    idxf[n0 + p1] = (float)bi1;
    atomicAdd(&g_counts[bi0], 1.0f);
    atomicAdd(&g_counts[bi1], 1.0f);

    float* zqp = zq + (size_t)b * D * HW + hw0;
#pragma unroll
    for (int d = 0; d < D; d++) {
        float zv0 = s_z[d * PTS + p0];
        float zv1 = s_z[d * PTS + p1];
        atomicAdd(&g_embupd[d * K + bi0], zv0);
        atomicAdd(&g_embupd[d * K + bi1], zv1);
        float2 o;
        o.x = emb[d * K + bi0];
        o.y = emb[d * K + bi1];
        *(float2*)(zqp + d * HW + p0) = o;     // p0 even -> 8B aligned
    }
}

// ---------------------------------------------------------------------------
// Kernel 2: EMA update + renorm.  <<<1, 1024>>>
// ---------------------------------------------------------------------------
__global__ void vq_finalize(const float* __restrict__ emb_ema,
                            const float* __restrict__ counts_ema,
                            float* __restrict__ out_emb_new,
                            float* __restrict__ out_emb_ema_new,
                            float* __restrict__ out_counts_new) {
    const float ALPHA = (float)(1.0 - 0.99);
    const float EPSF = 1e-5f;
    const float KEPS = (float)(1024.0 * 1e-5);

    __shared__ float red[1024];
    int k = threadIdx.x;

    float cen = counts_ema[k] + ALPHA * (g_counts[k] - counts_ema[k]);
    out_counts_new[k] = cen;

    red[k] = cen;
    __syncthreads();
#pragma unroll
    for (int s = 512; s > 0; s >>= 1) {
        if (k < s) red[k] += red[k + s];
        __syncthreads();
    }
    float nsum = red[0];

    float cn = (cen + EPSF) / (nsum + KEPS) * nsum;
    float inv = 1.0f / cn;

#pragma unroll
    for (int d = 0; d < D; d++) {
        float eu = g_embupd[d * K + k];
        float ee = emb_ema[d * K + k];
        float en = ee + ALPHA * (eu - ee);
        out_emb_ema_new[d * K + k] = en;
        out_emb_new[d * K + k] = en * inv;
    }
}

// ---------------------------------------------------------------------------
extern "C" void kernel_launch(void* const* d_in, const int* in_sizes, int n_in,
                              void* d_out, int out_size) {
    const float* z_e        = (const float*)d_in[0];
    const float* emb        = (const float*)d_in[1];
    const float* emb_ema    = (const float*)d_in[2];
    const float* counts_ema = (const float*)d_in[3];

    float* out = (float*)d_out;
    float* o_zq         = out;
    float* o_idx        = out + 4194304;
    float* o_emb_new    = out + 4194304 + 65536;
    float* o_emb_ema    = out + 4194304 + 2 * 65536;
    float* o_counts     = out + 4194304 + 3 * 65536;

    vq_prep<<<4, 256>>>(emb);
    vq_assign<<<N_POINTS / PTS, BTH>>>(z_e, emb, o_zq, o_idx);
    vq_finalize<<<1, 1024>>>(emb_ema, counts_ema, o_emb_new, o_emb_ema, o_counts);
}